// round 6
// baseline (speedup 1.0000x reference)
#include <cuda_runtime.h>

// ---------------------------------------------------------------------------
// SNN: 20 steps, batch 8192, 676 -> 256 (LIF) -> 10 (LIF)
// Outputs concatenated in tuple order: spk2, spk1, mem2, mem1 (fp32)
//
// Established facts (spk2 == 0.0 bitwise in rounds 4 & 5):
//   * reference is FULL fp32 (not tf32)
//   * bias after GEMM, LIF = separate mul/add, sub-threshold/sub-reset: exact
//   * reference layer-2 dot = serial ascending-k fp32 chain (matched bitwise)
// Remaining mismatch: layer-1 GEMM internal accumulation order (~20 flips).
// This round: layer-1 sum made near-EXACT (16-k tile chains + Kahan-
// compensated cross-tile fold, sigma ~1.3e-7) to isolate the reference's own
// rounding error. If reference uses short-chain (sliced-k) accumulation,
// this passes outright.
// ---------------------------------------------------------------------------

#define NS    20
#define BATCH 8192
#define NIN   676
#define NHID  256
#define NOUTN 10

#define KT  16
#define NKT 43          // ceil(676/16)
#define BM  128
#define BN  128

#define SPK2_OFF 0ull
#define SPK1_OFF (20ull*8192*10)
#define MEM2_OFF (SPK1_OFF + 20ull*8192*256)
#define MEM1_OFF (MEM2_OFF + 20ull*8192*10)

typedef unsigned long long u64;

__device__ __forceinline__ u64 bcast2(float x) {
    u64 r; asm("mov.b64 %0, {%1, %1};" : "=l"(r) : "f"(x)); return r;
}
__device__ __forceinline__ void upk2(u64 v, float& a, float& b) {
    asm("mov.b64 {%0, %1}, %2;" : "=f"(a), "=f"(b) : "l"(v));
}
__device__ __forceinline__ void fma2(u64& d, u64 a, u64 b) {
    asm("fma.rn.f32x2 %0, %1, %2, %0;" : "+l"(d) : "l"(a), "l"(b));
}
__device__ __forceinline__ u64 add2(u64 a, u64 b) {
    u64 r; asm("add.rn.f32x2 %0, %1, %2;" : "=l"(r) : "l"(a), "l"(b));
    return r;
}
// negate both packed floats (sign-bit xor); x + (-y) == x - y exactly (rn)
__device__ __forceinline__ u64 neg2(u64 a) {
    return a ^ 0x8000000080000000ull;
}

// ---------------------------------------------------------------------------
// Kernel 1: fused  h1 = x_t @ W1^T + b1 ; LIF over t  -> spk1, mem1
// Grid: (BATCH/BM, NHID/BN), 256 threads, 8x8 per-thread tile.
// Dynamic SMEM: 2 double-buffered 16x128 tiles for x and W (32 KB)
//               + persistent membrane 128x128 (64 KB)  = 96 KB
// Accumulation: per 16-k tile FMA chain (q), folded into (s, nc) with
// Neumaier/Kahan compensation; final h = s + c (c = -nc). Near-exact.
// ---------------------------------------------------------------------------
__global__ void __launch_bounds__(256, 1) snn_l1(
    const float* __restrict__ x, const float* __restrict__ W1,
    const float* __restrict__ b1, float* __restrict__ out)
{
    extern __shared__ float sm[];
    // layout: [buf0: xs 2048 | ws 2048][buf1: xs 2048 | ws 2048][m 16384]
    float* msm = sm + 8192;

    const int tid  = threadIdx.x;
    const int b0   = blockIdx.x * BM;
    const int n0   = blockIdx.y * BN;
    const int row0 = (tid >> 4) * 8;
    const int col0 = (tid & 15) * 8;

    // tile-load indices: both tiles are 128 rows x 16 k, float4 granularity
    const int li0 = tid >> 2;          // rows 0..63 ; second row = li0+64
    const int lk0 = (tid & 3) * 4;     // k offset within tile (0,4,8,12)

    // bias (added AFTER the K accumulation)
    float bcol[8];
#pragma unroll
    for (int j = 0; j < 8; j++) bcol[j] = b1[n0 + col0 + j];

    // init membrane (each thread owns its 64 elements, lane-contiguous layout)
#pragma unroll
    for (int e = 0; e < 64; e++) msm[e*256 + tid] = 0.0f;

    const float4 z4 = make_float4(0.f, 0.f, 0.f, 0.f);
    float4 xr0, xr1, wr0, wr1;

    // prefetch tile (t=0, kt=0)
    {
        const int k = lk0;  // kt=0, k < 676 always
        xr0 = *(const float4*)&x[(size_t)(b0 + li0)      * NIN + k];
        xr1 = *(const float4*)&x[(size_t)(b0 + li0 + 64) * NIN + k];
        wr0 = *(const float4*)&W1[(size_t)(n0 + li0)      * NIN + k];
        wr1 = *(const float4*)&W1[(size_t)(n0 + li0 + 64) * NIN + k];
    }
    {
        float* xs = sm;        float* ws = sm + 2048;
        xs[(lk0+0)*128 + li0] = xr0.x; xs[(lk0+1)*128 + li0] = xr0.y;
        xs[(lk0+2)*128 + li0] = xr0.z; xs[(lk0+3)*128 + li0] = xr0.w;
        xs[(lk0+0)*128 + li0+64] = xr1.x; xs[(lk0+1)*128 + li0+64] = xr1.y;
        xs[(lk0+2)*128 + li0+64] = xr1.z; xs[(lk0+3)*128 + li0+64] = xr1.w;
        ws[(lk0+0)*128 + li0] = wr0.x; ws[(lk0+1)*128 + li0] = wr0.y;
        ws[(lk0+2)*128 + li0] = wr0.z; ws[(lk0+3)*128 + li0] = wr0.w;
        ws[(lk0+0)*128 + li0+64] = wr1.x; ws[(lk0+1)*128 + li0+64] = wr1.y;
        ws[(lk0+2)*128 + li0+64] = wr1.z; ws[(lk0+3)*128 + li0+64] = wr1.w;
    }
    __syncthreads();

    u64 s[8][4];    // running sum
    u64 nc[8][4];   // NEGATED compensation (c = -nc); sum = s - nc
    int cur = 0, t = 0, kt = 0;

    for (int idx = 0; idx < NS * NKT; ++idx) {
        int nt = t, nkt = kt + 1;
        if (nkt == NKT) { nkt = 0; nt++; }
        const bool more = (idx + 1 < NS * NKT);

        // prefetch next tile into registers (latency hidden by compute)
        if (more) {
            const int k = nkt * KT + lk0;
            const float* xt = x + (size_t)nt * BATCH * NIN;
            if (k < NIN) {
                xr0 = *(const float4*)&xt[(size_t)(b0 + li0)      * NIN + k];
                xr1 = *(const float4*)&xt[(size_t)(b0 + li0 + 64) * NIN + k];
                wr0 = *(const float4*)&W1[(size_t)(n0 + li0)      * NIN + k];
                wr1 = *(const float4*)&W1[(size_t)(n0 + li0 + 64) * NIN + k];
            } else {
                xr0 = z4; xr1 = z4; wr0 = z4; wr1 = z4;
            }
        }

        if (kt == 0) {
#pragma unroll
            for (int i = 0; i < 8; i++)
#pragma unroll
                for (int jp = 0; jp < 4; jp++) { s[i][jp] = 0ull; nc[i][jp] = 0ull; }
        }

        // compute on current buffer: fresh per-tile accumulator q
        u64 q[8][4];
#pragma unroll
        for (int i = 0; i < 8; i++)
#pragma unroll
            for (int jp = 0; jp < 4; jp++) q[i][jp] = 0ull;
        {
            const float* xs = sm + cur * 4096;
            const float* ws = xs + 2048;
#pragma unroll
            for (int k = 0; k < KT; k++) {
                const float* xk = &xs[k*128 + row0];
                u64 xb[8];
                float2 p;
                p = *(const float2*)&xk[0]; xb[0] = bcast2(p.x); xb[1] = bcast2(p.y);
                p = *(const float2*)&xk[2]; xb[2] = bcast2(p.x); xb[3] = bcast2(p.y);
                p = *(const float2*)&xk[4]; xb[4] = bcast2(p.x); xb[5] = bcast2(p.y);
                p = *(const float2*)&xk[6]; xb[6] = bcast2(p.x); xb[7] = bcast2(p.y);
                const float* wk = &ws[k*128 + col0];
                u64 wp[4];
                wp[0] = *(const u64*)&wk[0];
                wp[1] = *(const u64*)&wk[2];
                wp[2] = *(const u64*)&wk[4];
                wp[3] = *(const u64*)&wk[6];
#pragma unroll
                for (int i = 0; i < 8; i++)
#pragma unroll
                    for (int jp = 0; jp < 4; jp++)
                        fma2(q[i][jp], xb[i], wp[jp]);
            }
        }
        // Kahan/Neumaier fold of tile sum q into (s, nc):
        //   y = q + nc; t = s + y; d = t - s; nc = y - d; s = t
#pragma unroll
        for (int i = 0; i < 8; i++)
#pragma unroll
            for (int jp = 0; jp < 4; jp++) {
                u64 y = add2(q[i][jp], nc[i][jp]);
                u64 tt = add2(s[i][jp], y);
                u64 d  = add2(tt, neg2(s[i][jp]));
                nc[i][jp] = add2(y, neg2(d));
                s[i][jp] = tt;
            }

        // end of K: LIF update for timestep t, write spk1 / mem1
        if (kt == NKT - 1) {
            const size_t ob = ((size_t)t * BATCH + (b0 + row0)) * NHID + n0 + col0;
#pragma unroll
            for (int i = 0; i < 8; i++) {
                float h[8];
#pragma unroll
                for (int jp = 0; jp < 4; jp++) {
                    u64 hs = add2(s[i][jp], neg2(nc[i][jp]));   // s + c
                    upk2(hs, h[2*jp], h[2*jp+1]);
                }
                float sv[8], mv[8];
#pragma unroll
                for (int j = 0; j < 8; j++) {
                    float hb = __fadd_rn(h[j], bcol[j]);        // gemm + bias (separate op)
                    float mm = msm[(i*8 + j)*256 + tid];
                    mm = __fadd_rn(__fmul_rn(0.9f, mm), hb);    // beta*m + h (mul, add)
                    float spk = (mm - 1.0f > 0.0f) ? 1.0f : 0.0f;
                    mm = __fadd_rn(mm, -spk);                    // soft reset (THR=1)
                    msm[(i*8 + j)*256 + tid] = mm;
                    sv[j] = spk; mv[j] = mm;
                }
                float* o1 = out + SPK1_OFF + ob + (size_t)i * NHID;
                *(float4*)&o1[0] = make_float4(sv[0], sv[1], sv[2], sv[3]);
                *(float4*)&o1[4] = make_float4(sv[4], sv[5], sv[6], sv[7]);
                float* o2 = out + MEM1_OFF + ob + (size_t)i * NHID;
                *(float4*)&o2[0] = make_float4(mv[0], mv[1], mv[2], mv[3]);
                *(float4*)&o2[4] = make_float4(mv[4], mv[5], mv[6], mv[7]);
            }
        }

        // stage next tile into the other buffer
        if (more) {
            float* xs = sm + (cur ^ 1) * 4096;
            float* ws = xs + 2048;
            xs[(lk0+0)*128 + li0] = xr0.x; xs[(lk0+1)*128 + li0] = xr0.y;
            xs[(lk0+2)*128 + li0] = xr0.z; xs[(lk0+3)*128 + li0] = xr0.w;
            xs[(lk0+0)*128 + li0+64] = xr1.x; xs[(lk0+1)*128 + li0+64] = xr1.y;
            xs[(lk0+2)*128 + li0+64] = xr1.z; xs[(lk0+3)*128 + li0+64] = xr1.w;
            ws[(lk0+0)*128 + li0] = wr0.x; ws[(lk0+1)*128 + li0] = wr0.y;
            ws[(lk0+2)*128 + li0] = wr0.z; ws[(lk0+3)*128 + li0] = wr0.w;
            ws[(lk0+0)*128 + li0+64] = wr1.x; ws[(lk0+1)*128 + li0+64] = wr1.y;
            ws[(lk0+2)*128 + li0+64] = wr1.z; ws[(lk0+3)*128 + li0+64] = wr1.w;
        }
        __syncthreads();
        cur ^= 1; t = nt; kt = nkt;
    }
}

// ---------------------------------------------------------------------------
// Kernel 2: fused  h2 = spk1_t @ W2^T + b2 ; LIF over t  -> spk2, mem2
// UNCHANGED (bit-exact: spk2 rel_err == 0.0 in rounds 4 and 5).
// ---------------------------------------------------------------------------
#define L2_THREADS 64

__global__ void __launch_bounds__(L2_THREADS) snn_l2(
    float* __restrict__ out, const float* __restrict__ W2,
    const float* __restrict__ b2)
{
    __shared__ float w2s[NOUTN * NHID];
    __shared__ float b2s[NOUTN];

    const int tid = threadIdx.x;
    for (int i = tid; i < NOUTN * NHID; i += L2_THREADS) w2s[i] = W2[i];
    if (tid < NOUTN) b2s[tid] = b2[tid];
    __syncthreads();

    const int row = blockIdx.x * L2_THREADS + tid;   // < 8192

    float m2[NOUTN];
#pragma unroll
    for (int o = 0; o < NOUTN; o++) m2[o] = 0.0f;

    for (int t = 0; t < NS; t++) {
        const float4* sp4 = (const float4*)(out + SPK1_OFF +
                             ((size_t)t * BATCH + row) * NHID);

        float acc[NOUTN];
#pragma unroll
        for (int o = 0; o < NOUTN; o++) acc[o] = 0.0f;

        // stream k in float4 chunks; per output o the FMA chain order is
        // strictly k = 0,1,2,...,255 into a single accumulator.
        for (int kc = 0; kc < NHID / 4; kc++) {
            float4 v = sp4[kc];
            const int kb = kc * 4;
#pragma unroll
            for (int o = 0; o < NOUTN; o++) {
                float a = acc[o];
                a = fmaf(v.x, w2s[o * NHID + kb + 0], a);
                a = fmaf(v.y, w2s[o * NHID + kb + 1], a);
                a = fmaf(v.z, w2s[o * NHID + kb + 2], a);
                a = fmaf(v.w, w2s[o * NHID + kb + 3], a);
                acc[o] = a;
            }
        }

        const size_t ob = ((size_t)t * BATCH + row) * NOUTN;
#pragma unroll
        for (int o = 0; o < NOUTN; o++) {
            float h = __fadd_rn(acc[o], b2s[o]);             // gemm + bias
            m2[o] = __fadd_rn(__fmul_rn(0.9f, m2[o]), h);    // beta*m + h
            float spk = (m2[o] - 1.0f > 0.0f) ? 1.0f : 0.0f;
            m2[o] = __fadd_rn(m2[o], -spk);                  // soft reset
            out[SPK2_OFF + ob + o] = spk;
            out[MEM2_OFF + ob + o] = m2[o];
        }
    }
}

// ---------------------------------------------------------------------------
extern "C" void kernel_launch(void* const* d_in, const int* in_sizes, int n_in,
                              void* d_out, int out_size)
{
    const float* x  = (const float*)d_in[0];
    const float* W1 = (const float*)d_in[1];
    const float* b1 = (const float*)d_in[2];
    const float* W2 = (const float*)d_in[3];
    const float* b2 = (const float*)d_in[4];
    float* out = (float*)d_out;

    cudaFuncSetAttribute(snn_l1, cudaFuncAttributeMaxDynamicSharedMemorySize,
                         96 * 1024);

    dim3 g1(BATCH / BM, NHID / BN);
    snn_l1<<<g1, 256, 96 * 1024>>>(x, W1, b1, out);
    snn_l2<<<BATCH / L2_THREADS, L2_THREADS>>>(out, W2, b2);
}